// round 14
// baseline (speedup 1.0000x reference)
#include <cuda_runtime.h>
#include <cuda_fp16.h>

typedef unsigned long long u64;
typedef unsigned int u32;
typedef unsigned short u16;

// ---------------- smem layout (bytes) ----------------
#define QHo   0        // Q/t fp16: 128 rows x 264 halves (stride 528B) = 67584
#define P0o   67584    // ping buffer (18432): plane0(9216)+plane1(9216)
#define P1o   86016    // pong buffer (18432)
#define CSTo  104448   // 1024 floats: bq(256) bg(256) bo(256) bc1(128) wc2(128)
#define SMEM_BYTES 108544

// ---------------- prepped global images (fp16) ----------------
// W images packed [kc][n][64]; elem bases: Wg=0, Wc1=65536, Wq=98304, Wo=163840
__device__ uint4 g_Wh_img[28672], g_Wl_img[28672];
__device__ uint4 g_knh[2][4][512];                   // normalized keys [s][d] 64x64 (hi only)
__device__ uint4 g_vth[2][4][512], g_vtl[2][4][512]; // values transposed [d][s] 64x64
// scratch for Phase-B half0 Q fragments: 32 planes x 131072 threads (16MB)
__device__ u32 g_qscr[32 * 131072];

// ---------------- helpers ----------------
__device__ __forceinline__ u32 pk2h(float x, float y) {   // lo=x, hi=y
    u32 r; asm("cvt.rn.f16x2.f32 %0, %1, %2;" : "=r"(r) : "f"(y), "f"(x)); return r;
}
__device__ __forceinline__ void sp2(float x, float y, u32& h, u32& l) {
    __half hx = __float2half_rn(x), hy = __float2half_rn(y);
    h = (u32)__half_as_ushort(hx) | ((u32)__half_as_ushort(hy) << 16);
    __half lx = __float2half_rn(x - __half2float(hx));
    __half ly = __float2half_rn(y - __half2float(hy));
    l = (u32)__half_as_ushort(lx) | ((u32)__half_as_ushort(ly) << 16);
}
__device__ __forceinline__ void spw(float v, u16& h, u16& l) {
    __half b = __float2half_rn(v);
    h = __half_as_ushort(b);
    l = __half_as_ushort(__float2half_rn(v - __half2float(b)));
}
__device__ __forceinline__ u32 smaddr(const void* p) {
    u32 a;
    asm("{ .reg .u64 t; cvta.to.shared.u64 t, %1; cvt.u32.u64 %0, t; }" : "=r"(a) : "l"(p));
    return a;
}
__device__ __forceinline__ void ldsm4(u32 a, u32& r0, u32& r1, u32& r2, u32& r3) {
    asm volatile("ldmatrix.sync.aligned.m8n8.x4.shared.b16 {%0,%1,%2,%3}, [%4];"
                 : "=r"(r0), "=r"(r1), "=r"(r2), "=r"(r3) : "r"(a));
}
__device__ __forceinline__ void mmab(float* c, u32 a0, u32 a1, u32 a2, u32 a3, u32 b0, u32 b1) {
    asm volatile(
        "mma.sync.aligned.m16n8k16.row.col.f32.f16.f16.f32 "
        "{%0,%1,%2,%3}, {%4,%5,%6,%7}, {%8,%9}, {%0,%1,%2,%3};"
        : "+f"(c[0]), "+f"(c[1]), "+f"(c[2]), "+f"(c[3])
        : "r"(a0), "r"(a1), "r"(a2), "r"(a3), "r"(b0), "r"(b1));
}
__device__ __forceinline__ float tanha(float x) {
    float y; asm("tanh.approx.f32 %0, %1;" : "=f"(y) : "f"(x)); return y;
}
#define CPA16(d, s) asm volatile("cp.async.cg.shared.global [%0], [%1], 16;" :: "r"(d), "l"(s) : "memory")
#define COMMIT()    asm volatile("cp.async.commit_group;" ::: "memory")
#define WAITG0()    asm volatile("cp.async.wait_group 0;" ::: "memory")
#define WAITG1()    asm volatile("cp.async.wait_group 1;" ::: "memory")

// prefetch one 64x64 W chunk into buffer p; LO = also copy lo plane (at +9216)
template<bool LO>
__device__ __forceinline__ void prefW(u32 p, u32 baseE, int tid) {
    const uint4* sH = g_Wh_img + (baseE >> 3);
    const uint4* sL = g_Wl_img + (baseE >> 3);
    #pragma unroll
    for (int i = tid; i < 512; i += 256) {
        u32 d = p + (u32)(i >> 3) * 144 + (u32)(i & 7) * 16;
        CPA16(d, (const void*)(sH + i));
        if (LO) CPA16(d + 9216, (const void*)(sL + i));
    }
    COMMIT();
}

// chunk c of a half (nbase): n in [nbase + (c>>2)*64, +64), kc = c&3
__device__ __forceinline__ u32 chunkE(u32 matBase, int nbase, int c, int N) {
    return matBase + (u32)((c & 3) * N + nbase + (c >> 2) * 64) * 64;
}

// one K=64 x N=64 stage: C[8][4] += A(16 rows) @ B(64 rows)^T
// TERMS: 1 = Ah@Bh, 2 = +Ah@Bl
template<int TERMS>
__device__ __forceinline__ void gemm_stage(float (*C)[4], u32 aH, u32 bH, u32 bL) {
    #pragma unroll
    for (int kt = 0; kt < 4; kt++) {
        u32 a0, a1, a2, a3;
        ldsm4(aH + kt * 32, a0, a1, a2, a3);
        #pragma unroll
        for (int np = 0; np < 4; np++) {
            u32 b0, b1, b2, b3, d0, d1, d2, d3;
            ldsm4(bH + np * 2304 + kt * 32, b0, b1, b2, b3);
            if (TERMS >= 2) ldsm4(bL + np * 2304 + kt * 32, d0, d1, d2, d3);
            mmab(C[2 * np], a0, a1, a2, a3, b0, b1);
            if (TERMS >= 2) mmab(C[2 * np], a0, a1, a2, a3, d0, d1);
            mmab(C[2 * np + 1], a0, a1, a2, a3, b2, b3);
            if (TERMS >= 2) mmab(C[2 * np + 1], a0, a1, a2, a3, d2, d3);
        }
    }
}

// pipelined half-sweep: 8 chunks (2 n-quarters x 4 kc) -> C[16][4]; prolog: chunks 0,1 committed
template<int TERMS>
__device__ __forceinline__ void sweep_half(float (*C)[4], u32 aH0, u32 bOff,
                                           u32 P0, u32 P1, u32 matBase, int nbase, int N, int tid) {
    #pragma unroll 1
    for (int c = 0; c < 8; c++) {
        if (c == 7) { WAITG0(); } else { WAITG1(); }
        __syncthreads();
        u32 pb = (c & 1) ? P1 : P0;
        gemm_stage<TERMS>(C + (c >> 2) * 8, aH0 + (u32)(c & 3) * 128, pb + bOff, pb + 9216 + bOff);
        if (c < 6) {
            __syncthreads();
            prefW<(TERMS >= 2)>(pb, chunkE(matBase, nbase, c + 2, N), tid);
        }
    }
    __syncthreads();
}

// stage fp32 [128x256] -> QBUF fp16 (stride 528)
__device__ __forceinline__ void stageQ(char* sma, const float* __restrict__ src, int tid) {
    #pragma unroll 4
    for (int i = tid; i < 8192; i += 256) {
        int r = i >> 6, c4 = i & 63;
        float4 v = *(const float4*)(src + (size_t)r * 256 + c4 * 4);
        u32 h0 = pk2h(v.x, v.y), h1 = pk2h(v.z, v.w);
        *(u64*)(sma + QHo + r * 528 + c4 * 8) = (u64)h0 | ((u64)h1 << 32);
    }
}

// ---------------- prep kernels ----------------
__global__ void prep_W(const float* __restrict__ Wq, const float* __restrict__ Wg,
                       const float* __restrict__ Wc1, const float* __restrict__ Wo) {
    int t = blockIdx.x * blockDim.x + threadIdx.x;   // 0..57343
    const float* src; int N; u32 base; int tt;
    if (t < 16384)      { src = Wg;  N = 256; base = 0u;      tt = t; }
    else if (t < 24576) { src = Wc1; N = 128; base = 65536u;  tt = t - 16384; }
    else if (t < 40960) { src = Wq;  N = 256; base = 98304u;  tt = t - 24576; }
    else                { src = Wo;  N = 256; base = 163840u; tt = t - 40960; }
    int n = tt >> 6, c4 = tt & 63;
    int kc = c4 >> 4, kk = (c4 & 15) * 4;
    float4 v = *(const float4*)(src + (size_t)n * 256 + c4 * 4);
    u32 h0, l0, h1, l1;
    sp2(v.x, v.y, h0, l0);
    sp2(v.z, v.w, h1, l1);
    u32 e = base + (u32)(kc * N + n) * 64 + (u32)kk;
    ((u64*)g_Wh_img)[e >> 2] = (u64)h0 | ((u64)h1 << 32);
    ((u64*)g_Wl_img)[e >> 2] = (u64)l0 | ((u64)l1 << 32);
}

__global__ void prep_kv(const float* __restrict__ fk, const float* __restrict__ fv,
                        const float* __restrict__ dk, const float* __restrict__ dv) {
    int t = blockIdx.x * blockDim.x + threadIdx.x;
    if (t >= 512) return;
    int tier = t >> 8, rem = t & 255, h = rem >> 6, s = rem & 63;
    const float* K = (tier ? dk : fk) + (h * 64 + s) * 64;
    const float* V = (tier ? dv : fv) + (h * 64 + s) * 64;
    float ss = 0.f;
    for (int d = 0; d < 64; d++) { float v = K[d]; ss += v * v; }
    float r = 1.0f / (sqrtf(ss) + 1e-8f);
    u16* knh = (u16*)g_knh[tier][h];
    u16* vth = (u16*)g_vth[tier][h]; u16* vtl = (u16*)g_vtl[tier][h];
    for (int d = 0; d < 64; d++) {
        u16 hh, ll;
        spw(K[d] * r, hh, ll);
        knh[s * 64 + d] = hh;
        spw(V[d], hh, ll);
        vth[d * 64 + s] = hh; vtl[d * 64 + s] = ll;
    }
}

// ---------------- main kernel (BM=128, 256 threads, 2 CTAs/SM) ----------------
__global__ void __launch_bounds__(256, 2) miras_mma(
    const float* __restrict__ query, const float* __restrict__ context,
    const float* __restrict__ bq, const float* __restrict__ bg,
    const float* __restrict__ bc1, const float* __restrict__ Wc2,
    const float* __restrict__ bc2, const float* __restrict__ bo,
    const float* __restrict__ mixl, float* __restrict__ outp)
{
    extern __shared__ char sma[];
    const u32 sb = smaddr(sma);
    const int tid = threadIdx.x, lane = tid & 31, warp = tid >> 5;
    const int mb = warp * 16;
    const size_t m0 = (size_t)blockIdx.x * 128;
    const u32 gtid = (u32)blockIdx.x * 256u + (u32)tid;
    float* cst = (float*)(sma + CSTo);
    const u32 P0 = sb + P0o, P1 = sb + P1o;

    { int i = tid; cst[i] = bq[i]; cst[256 + i] = bg[i]; cst[512 + i] = bo[i]; }
    if (tid < 128) { cst[768 + tid] = bc1[tid]; cst[896 + tid] = Wc2[tid]; }
    const float mixl_v = __ldg(mixl), bc2v = __ldg(bc2);

    // lane-resolved ldmatrix offsets
    const u32 arow = (u32)(((lane >> 3) & 1) * 8 + (lane & 7));
    const u32 aOffQ = (u32)(mb + arow) * 528 + (u32)(lane >> 4) * 16;
    const u32 bOff  = (u32)(((lane >> 4) & 1) * 8 + (lane & 7)) * 144 + (u32)((lane >> 3) & 1) * 16;
    const u32 qH0 = sb + QHo + aOffQ;

    float C[16][4];

    // ---------- Phase A: gate (N=256, 1-term fp16, two half-sweeps; no write-back) ----------
    prefW<false>(P0, chunkE(0u, 0, 0, 256), tid);
    prefW<false>(P1, chunkE(0u, 0, 1, 256), tid);
    stageQ(sma, context + m0 * 256, tid);
    float ga0 = 0.f, ga1 = 0.f;
    #pragma unroll 1
    for (int half = 0; half < 2; half++) {
        #pragma unroll
        for (int t = 0; t < 16; t++) { C[t][0] = C[t][1] = C[t][2] = C[t][3] = 0.f; }
        sweep_half<1>(C, qH0, bOff, P0, P1, 0u, half * 128, 256, tid);
        if (half == 0) {
            prefW<false>(P0, chunkE(0u, 128, 0, 256), tid);
            prefW<false>(P1, chunkE(0u, 128, 1, 256), tid);
        } else {
            prefW<true>(P0, chunkE(65536u, 0, 0, 128), tid);
            prefW<true>(P1, chunkE(65536u, 0, 1, 128), tid);
        }
        #pragma unroll
        for (int t = 0; t < 16; t++) {
            int col = half * 128 + (t >> 3) * 64 + (t & 7) * 8 + (lane & 3) * 2;
            ga0 += tanha(C[t][0] + cst[256 + col]) + tanha(C[t][1] + cst[256 + col + 1]);
            ga1 += tanha(C[t][2] + cst[256 + col]) + tanha(C[t][3] + cst[256 + col + 1]);
        }
    }

    // ---------- conf (N=128, 2-term fp16; no write-back) ----------
    #pragma unroll
    for (int t = 0; t < 16; t++) { C[t][0] = C[t][1] = C[t][2] = C[t][3] = 0.f; }
    sweep_half<2>(C, qH0, bOff, P0, P1, 65536u, 0, 128, tid);
    prefW<true>(P0, chunkE(98304u, 0, 0, 256), tid);   // Wq half0 prolog
    prefW<true>(P1, chunkE(98304u, 0, 1, 256), tid);

    float ca0 = 0.f, ca1 = 0.f;
    #pragma unroll
    for (int t = 0; t < 16; t++) {
        int col = (t >> 3) * 64 + (t & 7) * 8 + (lane & 3) * 2;
        ca0 += tanha(C[t][0] + cst[768 + col]) * cst[896 + col]
             + tanha(C[t][1] + cst[768 + col + 1]) * cst[896 + col + 1];
        ca1 += tanha(C[t][2] + cst[768 + col]) * cst[896 + col]
             + tanha(C[t][3] + cst[768 + col + 1]) * cst[896 + col + 1];
    }
    ga0 += __shfl_xor_sync(0xffffffffu, ga0, 1); ga0 += __shfl_xor_sync(0xffffffffu, ga0, 2);
    ga1 += __shfl_xor_sync(0xffffffffu, ga1, 1); ga1 += __shfl_xor_sync(0xffffffffu, ga1, 2);
    ca0 += __shfl_xor_sync(0xffffffffu, ca0, 1); ca0 += __shfl_xor_sync(0xffffffffu, ca0, 2);
    ca1 += __shfl_xor_sync(0xffffffffu, ca1, 1); ca1 += __shfl_xor_sync(0xffffffffu, ca1, 2);
    float mix0 = 1.f / (1.f + __expf(-(mixl_v + ga0 * (1.f / 256.f))));
    float mix1 = 1.f / (1.f + __expf(-(mixl_v + ga1 * (1.f / 256.f))));
    float cf0 = 1.f / (1.f + __expf(-(ca0 + bc2v)));
    float cf1 = 1.f / (1.f + __expf(-(ca1 + bc2v)));
    float aF0 = mix0 * cf0, aD0 = (1.f - mix0) * cf0;
    float aF1 = mix1 * cf1, aD1 = (1.f - mix1) * cf1;

    // ---------- Phase B: Q = query @ Wq^T + bq (N=256, 2-term, two half-sweeps) ----------
    // half0 output goes to global scratch (QBUF still holds the query = A operand for half1!)
    stageQ(sma, query + m0 * 256, tid);              // safe: conf sweep ended with sync
    float ssqA[4] = {0.f, 0.f, 0.f, 0.f}, ssqB[4] = {0.f, 0.f, 0.f, 0.f};

    #pragma unroll
    for (int t = 0; t < 16; t++) { C[t][0] = C[t][1] = C[t][2] = C[t][3] = 0.f; }
    sweep_half<2>(C, qH0, bOff, P0, P1, 98304u, 0, 256, tid);
    prefW<true>(P0, chunkE(98304u, 128, 0, 256), tid);
    prefW<true>(P1, chunkE(98304u, 128, 1, 256), tid);
    #pragma unroll
    for (int t = 0; t < 16; t++) {
        int col = (t >> 3) * 64 + (t & 7) * 8 + (lane & 3) * 2;
        float v0 = C[t][0] + cst[col], v1 = C[t][1] + cst[col + 1];
        float v2 = C[t][2] + cst[col], v3 = C[t][3] + cst[col + 1];
        int hh = t >> 3;
        ssqA[hh] += v0 * v0 + v1 * v1;
        ssqB[hh] += v2 * v2 + v3 * v3;
        g_qscr[(u32)(2 * t) * 131072u + gtid]     = pk2h(v0, v1);
        g_qscr[(u32)(2 * t + 1) * 131072u + gtid] = pk2h(v2, v3);
    }

    #pragma unroll
    for (int t = 0; t < 16; t++) { C[t][0] = C[t][1] = C[t][2] = C[t][3] = 0.f; }
    sweep_half<2>(C, qH0, bOff, P0, P1, 98304u, 128, 256, tid);
    // half1 epilogue: write cols 128..255 into QBUF (query fully consumed now)
    #pragma unroll
    for (int t = 0; t < 16; t++) {
        int col = 128 + (t >> 3) * 64 + (t & 7) * 8 + (lane & 3) * 2;
        float v0 = C[t][0] + cst[col], v1 = C[t][1] + cst[col + 1];
        float v2 = C[t][2] + cst[col], v3 = C[t][3] + cst[col + 1];
        int hh = 2 + (t >> 3);
        ssqA[hh] += v0 * v0 + v1 * v1;
        ssqB[hh] += v2 * v2 + v3 * v3;
        char* p = sma + QHo + (mb + (lane >> 2)) * 528 + col * 2;
        *(u32*)p = pk2h(v0, v1);
        *(u32*)(p + 8 * 528) = pk2h(v2, v3);
    }
    // reload half0 from scratch (same thread wrote it) and write cols 0..127
    #pragma unroll
    for (int t = 0; t < 16; t++) {
        int col = (t >> 3) * 64 + (t & 7) * 8 + (lane & 3) * 2;
        char* p = sma + QHo + (mb + (lane >> 2)) * 528 + col * 2;
        *(u32*)p = g_qscr[(u32)(2 * t) * 131072u + gtid];
        *(u32*)(p + 8 * 528) = g_qscr[(u32)(2 * t + 1) * 131072u + gtid];
    }
    float rqA[4], rqB[4];
    #pragma unroll
    for (int hh = 0; hh < 4; hh++) {
        float s = ssqA[hh];
        s += __shfl_xor_sync(0xffffffffu, s, 1); s += __shfl_xor_sync(0xffffffffu, s, 2);
        rqA[hh] = 1.f / (sqrtf(s) + 1e-8f);
        s = ssqB[hh];
        s += __shfl_xor_sync(0xffffffffu, s, 1); s += __shfl_xor_sync(0xffffffffu, s, 2);
        rqB[hh] = 1.f / (sqrtf(s) + 1e-8f);
    }
    __syncthreads();

    // ---------- Phase C: dual-tier attention, per (h, tier): kn->P0, v->P1 ----------
    float T[8][4];
    #pragma unroll 1
    for (int it = 0; it < 8; it++) {
        const int h = it >> 1, tier = it & 1;
        __syncthreads();   // previous iteration's tiles fully consumed
        {
            const uint4* s0 = g_knh[tier][h];
            const uint4* s1 = g_vth[tier][h];
            const uint4* s2 = g_vtl[tier][h];
            #pragma unroll
            for (int i = tid; i < 512; i += 256) {
                u32 d = (u32)(i >> 3) * 144 + (u32)(i & 7) * 16;
                CPA16(P0 + d,        (const void*)(s0 + i));
                CPA16(P1 + d,        (const void*)(s1 + i));
                CPA16(P1 + 9216 + d, (const void*)(s2 + i));
            }
            COMMIT();
            WAITG0();
        }
        __syncthreads();

        if (tier == 0) {
            #pragma unroll
            for (int t = 0; t < 8; t++) { T[t][0] = T[t][1] = T[t][2] = T[t][3] = 0.f; }
        }
        float rq0 = rqA[h], rq1 = rqB[h];
        float sc0 = tier ? aD0 : aF0, sc1 = tier ? aD1 : aF1;

        // sim = Q_h @ kn^T (1-term fp16)
        float S[8][4];
        #pragma unroll
        for (int t = 0; t < 8; t++) { S[t][0] = S[t][1] = S[t][2] = S[t][3] = 0.f; }
        gemm_stage<1>(S, qH0 + (u32)h * 128, P0 + bOff, P0 + bOff);

        float mx0 = -1e30f, mx1 = -1e30f;
        #pragma unroll
        for (int t = 0; t < 8; t++) {
            S[t][0] *= rq0; S[t][1] *= rq0; S[t][2] *= rq1; S[t][3] *= rq1;
            mx0 = fmaxf(mx0, fmaxf(S[t][0], S[t][1]));
            mx1 = fmaxf(mx1, fmaxf(S[t][2], S[t][3]));
        }
        mx0 = fmaxf(mx0, __shfl_xor_sync(0xffffffffu, mx0, 1));
        mx0 = fmaxf(mx0, __shfl_xor_sync(0xffffffffu, mx0, 2));
        mx1 = fmaxf(mx1, __shfl_xor_sync(0xffffffffu, mx1, 1));
        mx1 = fmaxf(mx1, __shfl_xor_sync(0xffffffffu, mx1, 2));
        float su0 = 0.f, su1 = 0.f;
        #pragma unroll
        for (int t = 0; t < 8; t++) {
            S[t][0] = __expf(S[t][0] - mx0); S[t][1] = __expf(S[t][1] - mx0);
            S[t][2] = __expf(S[t][2] - mx1); S[t][3] = __expf(S[t][3] - mx1);
            su0 += S[t][0] + S[t][1];
            su1 += S[t][2] + S[t][3];
        }
        su0 += __shfl_xor_sync(0xffffffffu, su0, 1); su0 += __shfl_xor_sync(0xffffffffu, su0, 2);
        su1 += __shfl_xor_sync(0xffffffffu, su1, 1); su1 += __shfl_xor_sync(0xffffffffu, su1, 2);
        float iv0 = sc0 / su0, iv1 = sc1 / su1;

        u32 pH[8][2];
        #pragma unroll
        for (int t = 0; t < 8; t++) {
            pH[t][0] = pk2h(S[t][0] * iv0, S[t][1] * iv0);
            pH[t][1] = pk2h(S[t][2] * iv1, S[t][3] * iv1);
        }

        // T += P @ V (2-term fp16: Ph@Vh + Ph@Vl)
        #pragma unroll
        for (int kt = 0; kt < 4; kt++) {
            u32 a0 = pH[2*kt][0], a1 = pH[2*kt][1], a2 = pH[2*kt+1][0], a3 = pH[2*kt+1][1];
            #pragma unroll
            for (int np = 0; np < 4; np++) {
                u32 b0, b1, b2, b3, d0, d1, d2, d3;
                ldsm4(P1 + bOff + np * 2304 + kt * 32, b0, b1, b2, b3);
                ldsm4(P1 + 9216 + bOff + np * 2304 + kt * 32, d0, d1, d2, d3);
                mmab(T[2*np],   a0, a1, a2, a3, b0, b1);
                mmab(T[2*np],   a0, a1, a2, a3, d0, d1);
                mmab(T[2*np+1], a0, a1, a2, a3, b2, b3);
                mmab(T[2*np+1], a0, a1, a2, a3, d2, d3);
            }
        }

        if (tier == 1) {
            // write t_h (fp16) over Q_h in QBUF (own rows only; Q_h fully consumed)
            #pragma unroll
            for (int t = 0; t < 8; t++) {
                int col = h * 64 + t * 8 + (lane & 3) * 2;
                char* p = sma + QHo + (mb + (lane >> 2)) * 528 + col * 2;
                *(u32*)p = pk2h(T[t][0], T[t][1]);
                *(u32*)(p + 8 * 528) = pk2h(T[t][2], T[t][3]);
            }
            __syncwarp();
        }
    }
    __syncthreads();

    // ---------- Phase D: out = t @ Wo^T + bo (N=256, 2-term, two half-sweeps; no write-back) ----------
    prefW<true>(P0, chunkE(163840u, 0, 0, 256), tid);
    prefW<true>(P1, chunkE(163840u, 0, 1, 256), tid);
    #pragma unroll 1
    for (int half = 0; half < 2; half++) {
        #pragma unroll
        for (int t = 0; t < 16; t++) { C[t][0] = C[t][1] = C[t][2] = C[t][3] = 0.f; }
        sweep_half<2>(C, qH0, bOff, P0, P1, 163840u, half * 128, 256, tid);
        if (half == 0) {
            prefW<true>(P0, chunkE(163840u, 128, 0, 256), tid);
            prefW<true>(P1, chunkE(163840u, 128, 1, 256), tid);
        }
        #pragma unroll
        for (int t = 0; t < 16; t++) {
            int col = half * 128 + (t >> 3) * 64 + (t & 7) * 8 + (lane & 3) * 2;
            size_t r0 = m0 + mb + (lane >> 2);
            float2 o0 = make_float2(C[t][0] + cst[512 + col], C[t][1] + cst[512 + col + 1]);
            *(float2*)(outp + r0 * 256 + col) = o0;
            float2 o1 = make_float2(C[t][2] + cst[512 + col], C[t][3] + cst[512 + col + 1]);
            *(float2*)(outp + (r0 + 8) * 256 + col) = o1;
        }
    }
}

extern "C" void kernel_launch(void* const* d_in, const int* in_sizes, int n_in,
                              void* d_out, int out_size) {
    (void)in_sizes; (void)n_in; (void)out_size;
    const float* query   = (const float*)d_in[0];
    const float* context = (const float*)d_in[1];
    const float* fk  = (const float*)d_in[2];
    const float* fv  = (const float*)d_in[3];
    const float* dk  = (const float*)d_in[4];
    const float* dv  = (const float*)d_in[5];
    const float* Wq  = (const float*)d_in[6];
    const float* bq  = (const float*)d_in[7];
    const float* Wg  = (const float*)d_in[8];
    const float* bg  = (const float*)d_in[9];
    const float* Wc1 = (const float*)d_in[10];
    const float* bc1 = (const float*)d_in[11];
    const float* Wc2 = (const float*)d_in[12];
    const float* bc2 = (const float*)d_in[13];
    const float* Wo  = (const float*)d_in[14];
    const float* bo  = (const float*)d_in[15];
    const float* mixl = (const float*)d_in[18];
    float* out = (float*)d_out;

    cudaFuncSetAttribute(miras_mma, cudaFuncAttributeMaxDynamicSharedMemorySize, SMEM_BYTES);

    prep_W<<<224, 256>>>(Wq, Wg, Wc1, Wo);
    prep_kv<<<2, 256>>>(fk, fv, dk, dv);
    miras_mma<<<512, 256, SMEM_BYTES>>>(query, context, bq, bg, bc1, Wc2, bc2, bo, mixl, out);
}

// round 15
// speedup vs baseline: 1.5593x; 1.5593x over previous
#include <cuda_runtime.h>
#include <cuda_fp16.h>

typedef unsigned long long u64;
typedef unsigned int u32;
typedef unsigned short u16;

// ---------------- smem layout (bytes) ----------------
#define QHo   0        // Q/t fp16: 128 rows x 264 halves (stride 528B) = 67584
#define P0o   67584    // ping buffer (36864): W chunk hi(18432)+lo(18432) / attn tiles
#define P1o   104448   // pong buffer (36864)
#define CSTo  141312   // 1024 floats: bq(256) bg(256) bo(256) bc1(128) wc2(128)
#define SMEM_BYTES 145408

// ---------------- prepped global images (fp16) ----------------
// W images packed [kc][n][64]; elem bases: Wg=0, Wc1=65536, Wq=98304, Wo=163840
__device__ uint4 g_Wh_img[28672], g_Wl_img[28672];
__device__ uint4 g_knh[2][4][512];                   // normalized keys [s][d] 64x64 (hi only)
__device__ uint4 g_vth[2][4][512], g_vtl[2][4][512]; // values transposed [d][s] 64x64

// ---------------- helpers ----------------
__device__ __forceinline__ u32 pk2h(float x, float y) {   // lo=x, hi=y
    u32 r; asm("cvt.rn.f16x2.f32 %0, %1, %2;" : "=r"(r) : "f"(y), "f"(x)); return r;
}
__device__ __forceinline__ void sp2(float x, float y, u32& h, u32& l) {
    __half hx = __float2half_rn(x), hy = __float2half_rn(y);
    h = (u32)__half_as_ushort(hx) | ((u32)__half_as_ushort(hy) << 16);
    __half lx = __float2half_rn(x - __half2float(hx));
    __half ly = __float2half_rn(y - __half2float(hy));
    l = (u32)__half_as_ushort(lx) | ((u32)__half_as_ushort(ly) << 16);
}
__device__ __forceinline__ void spw(float v, u16& h, u16& l) {
    __half b = __float2half_rn(v);
    h = __half_as_ushort(b);
    l = __half_as_ushort(__float2half_rn(v - __half2float(b)));
}
__device__ __forceinline__ u32 smaddr(const void* p) {
    u32 a;
    asm("{ .reg .u64 t; cvta.to.shared.u64 t, %1; cvt.u32.u64 %0, t; }" : "=r"(a) : "l"(p));
    return a;
}
__device__ __forceinline__ void ldsm4(u32 a, u32& r0, u32& r1, u32& r2, u32& r3) {
    asm volatile("ldmatrix.sync.aligned.m8n8.x4.shared.b16 {%0,%1,%2,%3}, [%4];"
                 : "=r"(r0), "=r"(r1), "=r"(r2), "=r"(r3) : "r"(a));
}
__device__ __forceinline__ void mmab(float* c, u32 a0, u32 a1, u32 a2, u32 a3, u32 b0, u32 b1) {
    asm volatile(
        "mma.sync.aligned.m16n8k16.row.col.f32.f16.f16.f32 "
        "{%0,%1,%2,%3}, {%4,%5,%6,%7}, {%8,%9}, {%0,%1,%2,%3};"
        : "+f"(c[0]), "+f"(c[1]), "+f"(c[2]), "+f"(c[3])
        : "r"(a0), "r"(a1), "r"(a2), "r"(a3), "r"(b0), "r"(b1));
}
__device__ __forceinline__ float tanha(float x) {
    float y; asm("tanh.approx.f32 %0, %1;" : "=f"(y) : "f"(x)); return y;
}
#define CPA16(d, s) asm volatile("cp.async.cg.shared.global [%0], [%1], 16;" :: "r"(d), "l"(s) : "memory")
#define COMMIT()    asm volatile("cp.async.commit_group;" ::: "memory")
#define WAITG0()    asm volatile("cp.async.wait_group 0;" ::: "memory")
#define WAITG1()    asm volatile("cp.async.wait_group 1;" ::: "memory")

// prefetch one 128x64 W chunk into buffer p; LO = also copy the lo plane
template<bool LO>
__device__ __forceinline__ void prefW(u32 p, u32 baseE, int tid) {
    const uint4* sH = g_Wh_img + (baseE >> 3);
    const uint4* sL = g_Wl_img + (baseE >> 3);
    #pragma unroll
    for (int i = tid; i < 1024; i += 256) {
        u32 d = p + (u32)(i >> 3) * 144 + (u32)(i & 7) * 16;
        CPA16(d, (const void*)(sH + i));
        if (LO) CPA16(d + 18432, (const void*)(sL + i));
    }
    COMMIT();
}

// one K=64 stage: C[2*NP][4] += A(16 rows,64 cols) @ B(NP*16 rows,64 cols)^T
// TERMS: 1 = Ah@Bh, 2 = +Ah@Bl   (A lo plane never read)
template<int NP, int TERMS>
__device__ __forceinline__ void gemm_stage(float (*C)[4], u32 aH, u32 bH, u32 bL) {
    #pragma unroll
    for (int kt = 0; kt < 4; kt++) {
        u32 a0, a1, a2, a3;
        ldsm4(aH + kt * 32, a0, a1, a2, a3);
        #pragma unroll
        for (int np = 0; np < NP; np++) {
            u32 b0, b1, b2, b3, d0, d1, d2, d3;
            ldsm4(bH + np * 2304 + kt * 32, b0, b1, b2, b3);
            if (TERMS >= 2) ldsm4(bL + np * 2304 + kt * 32, d0, d1, d2, d3);
            mmab(C[2 * np], a0, a1, a2, a3, b0, b1);
            if (TERMS >= 2) mmab(C[2 * np], a0, a1, a2, a3, d0, d1);
            mmab(C[2 * np + 1], a0, a1, a2, a3, b2, b3);
            if (TERMS >= 2) mmab(C[2 * np + 1], a0, a1, a2, a3, d2, d3);
        }
    }
}

// dual-half sweep (N=256): 8 chunks, C[0..15]=half0, C[16..31]=half1; prolog chunks 0,1 committed
template<int TERMS>
__device__ __forceinline__ void sweep_dual(float (*C)[4], u32 aH0, u32 bOff,
                                           u32 P0, u32 P1, u32 baseE, int tid) {
    #pragma unroll 1
    for (int kc = 0; kc < 4; kc++) {
        WAITG1();
        __syncthreads();
        gemm_stage<8, TERMS>(C, aH0 + (u32)kc * 128, P0 + bOff, P0 + 18432 + bOff);
        if (kc < 3) { __syncthreads(); prefW<(TERMS >= 2)>(P0, baseE + (u32)(kc * 2 + 2) * 8192, tid); }
        if (kc == 3) { WAITG0(); } else { WAITG1(); }
        __syncthreads();
        gemm_stage<8, TERMS>(C + 16, aH0 + (u32)kc * 128, P1 + bOff, P1 + 18432 + bOff);
        if (kc < 3) { __syncthreads(); prefW<(TERMS >= 2)>(P1, baseE + (u32)(kc * 2 + 3) * 8192, tid); }
    }
    __syncthreads();
}

// single-half sweep (N=128): 4 chunks into one C set; prolog chunks 0,1 committed
template<int TERMS>
__device__ __forceinline__ void sweep_single(float (*C)[4], u32 aH0, u32 bOff,
                                             u32 P0, u32 P1, u32 baseE, int tid) {
    #pragma unroll 1
    for (int s = 0; s < 4; s++) {
        if (s == 3) { WAITG0(); } else { WAITG1(); }
        __syncthreads();
        u32 pb = (s & 1) ? P1 : P0;
        gemm_stage<8, TERMS>(C, aH0 + (u32)s * 128, pb + bOff, pb + 18432 + bOff);
        if (s < 2) { __syncthreads(); prefW<(TERMS >= 2)>(pb, baseE + (u32)(s + 2) * 8192, tid); }
    }
    __syncthreads();
}

// stage fp32 [128x256] -> QBUF fp16 hi (stride 528)
__device__ __forceinline__ void stageQ(char* sma, const float* __restrict__ src, int tid) {
    #pragma unroll 4
    for (int i = tid; i < 8192; i += 256) {
        int r = i >> 6, c4 = i & 63;
        float4 v = *(const float4*)(src + (size_t)r * 256 + c4 * 4);
        u32 h0 = pk2h(v.x, v.y), h1 = pk2h(v.z, v.w);
        *(u64*)(sma + QHo + r * 528 + c4 * 8) = (u64)h0 | ((u64)h1 << 32);
    }
}

// ---------------- prep kernels ----------------
__global__ void prep_W(const float* __restrict__ Wq, const float* __restrict__ Wg,
                       const float* __restrict__ Wc1, const float* __restrict__ Wo) {
    int t = blockIdx.x * blockDim.x + threadIdx.x;   // 0..57343
    const float* src; int N; u32 base; int tt;
    if (t < 16384)      { src = Wg;  N = 256; base = 0u;      tt = t; }
    else if (t < 24576) { src = Wc1; N = 128; base = 65536u;  tt = t - 16384; }
    else if (t < 40960) { src = Wq;  N = 256; base = 98304u;  tt = t - 24576; }
    else                { src = Wo;  N = 256; base = 163840u; tt = t - 40960; }
    int n = tt >> 6, c4 = tt & 63;
    int kc = c4 >> 4, kk = (c4 & 15) * 4;
    float4 v = *(const float4*)(src + (size_t)n * 256 + c4 * 4);
    u32 h0, l0, h1, l1;
    sp2(v.x, v.y, h0, l0);
    sp2(v.z, v.w, h1, l1);
    u32 e = base + (u32)(kc * N + n) * 64 + (u32)kk;
    ((u64*)g_Wh_img)[e >> 2] = (u64)h0 | ((u64)h1 << 32);
    ((u64*)g_Wl_img)[e >> 2] = (u64)l0 | ((u64)l1 << 32);
}

__global__ void prep_kv(const float* __restrict__ fk, const float* __restrict__ fv,
                        const float* __restrict__ dk, const float* __restrict__ dv) {
    int t = blockIdx.x * blockDim.x + threadIdx.x;
    if (t >= 512) return;
    int tier = t >> 8, rem = t & 255, h = rem >> 6, s = rem & 63;
    const float* K = (tier ? dk : fk) + (h * 64 + s) * 64;
    const float* V = (tier ? dv : fv) + (h * 64 + s) * 64;
    float ss = 0.f;
    for (int d = 0; d < 64; d++) { float v = K[d]; ss += v * v; }
    float r = 1.0f / (sqrtf(ss) + 1e-8f);
    u16* knh = (u16*)g_knh[tier][h];
    u16* vth = (u16*)g_vth[tier][h]; u16* vtl = (u16*)g_vtl[tier][h];
    for (int d = 0; d < 64; d++) {
        u16 hh, ll;
        spw(K[d] * r, hh, ll);
        knh[s * 64 + d] = hh;
        spw(V[d], hh, ll);
        vth[d * 64 + s] = hh; vtl[d * 64 + s] = ll;
    }
}

// ---------------- main kernel ----------------
__global__ void __launch_bounds__(256, 1) miras_mma(
    const float* __restrict__ query, const float* __restrict__ context,
    const float* __restrict__ bq, const float* __restrict__ bg,
    const float* __restrict__ bc1, const float* __restrict__ Wc2,
    const float* __restrict__ bc2, const float* __restrict__ bo,
    const float* __restrict__ mixl, float* __restrict__ outp)
{
    extern __shared__ char sma[];
    const u32 sb = smaddr(sma);
    const int tid = threadIdx.x, lane = tid & 31, warp = tid >> 5;
    const int mb = warp * 16;
    const size_t m0 = (size_t)blockIdx.x * 128;
    float* cst = (float*)(sma + CSTo);
    const u32 P0 = sb + P0o, P1 = sb + P1o;

    { int i = tid; cst[i] = bq[i]; cst[256 + i] = bg[i]; cst[512 + i] = bo[i]; }
    if (tid < 128) { cst[768 + tid] = bc1[tid]; cst[896 + tid] = Wc2[tid]; }
    const float mixl_v = __ldg(mixl), bc2v = __ldg(bc2);

    // lane-resolved ldmatrix offsets
    const u32 arow = (u32)(((lane >> 3) & 1) * 8 + (lane & 7));
    const u32 aOffQ = (u32)(mb + arow) * 528 + (u32)(lane >> 4) * 16;
    const u32 bOff  = (u32)(((lane >> 4) & 1) * 8 + (lane & 7)) * 144 + (u32)((lane >> 3) & 1) * 16;
    const u32 qH0 = sb + QHo + aOffQ;

    float C[32][4];

    // ---------- Phase A: gate (N=256, 1-term fp16) ----------
    prefW<false>(P0, 0u, tid);
    prefW<false>(P1, 8192u, tid);
    stageQ(sma, context + m0 * 256, tid);
    #pragma unroll
    for (int t = 0; t < 32; t++) { C[t][0] = C[t][1] = C[t][2] = C[t][3] = 0.f; }
    sweep_dual<1>(C, qH0, bOff, P0, P1, 0u, tid);

    float ga0 = 0.f, ga1 = 0.f;
    #pragma unroll
    for (int t = 0; t < 32; t++) {
        int col = (t >> 4) * 128 + (t & 15) * 8 + (lane & 3) * 2;
        ga0 += tanha(C[t][0] + cst[256 + col]) + tanha(C[t][1] + cst[256 + col + 1]);
        ga1 += tanha(C[t][2] + cst[256 + col]) + tanha(C[t][3] + cst[256 + col + 1]);
    }

    // ---------- conf (N=128, 2-term fp16) ----------
    prefW<true>(P0, 65536u, tid);
    prefW<true>(P1, 65536u + 8192u, tid);
    #pragma unroll
    for (int t = 0; t < 16; t++) { C[t][0] = C[t][1] = C[t][2] = C[t][3] = 0.f; }
    sweep_single<2>(C, qH0, bOff, P0, P1, 65536u, tid);

    float ca0 = 0.f, ca1 = 0.f;
    #pragma unroll
    for (int t = 0; t < 16; t++) {
        int col = t * 8 + (lane & 3) * 2;
        ca0 += tanha(C[t][0] + cst[768 + col]) * cst[896 + col]
             + tanha(C[t][1] + cst[768 + col + 1]) * cst[896 + col + 1];
        ca1 += tanha(C[t][2] + cst[768 + col]) * cst[896 + col]
             + tanha(C[t][3] + cst[768 + col + 1]) * cst[896 + col + 1];
    }
    ga0 += __shfl_xor_sync(0xffffffffu, ga0, 1); ga0 += __shfl_xor_sync(0xffffffffu, ga0, 2);
    ga1 += __shfl_xor_sync(0xffffffffu, ga1, 1); ga1 += __shfl_xor_sync(0xffffffffu, ga1, 2);
    ca0 += __shfl_xor_sync(0xffffffffu, ca0, 1); ca0 += __shfl_xor_sync(0xffffffffu, ca0, 2);
    ca1 += __shfl_xor_sync(0xffffffffu, ca1, 1); ca1 += __shfl_xor_sync(0xffffffffu, ca1, 2);
    float mix0 = 1.f / (1.f + __expf(-(mixl_v + ga0 * (1.f / 256.f))));
    float mix1 = 1.f / (1.f + __expf(-(mixl_v + ga1 * (1.f / 256.f))));
    float cf0 = 1.f / (1.f + __expf(-(ca0 + bc2v)));
    float cf1 = 1.f / (1.f + __expf(-(ca1 + bc2v)));
    float aF0 = mix0 * cf0, aD0 = (1.f - mix0) * cf0;
    float aF1 = mix1 * cf1, aD1 = (1.f - mix1) * cf1;

    // ---------- Phase B: Q = query @ Wq^T + bq (N=256, 1-term fp16) ----------
    prefW<false>(P0, 98304u, tid);
    prefW<false>(P1, 98304u + 8192u, tid);
    stageQ(sma, query + m0 * 256, tid);          // safe: conf sweep ended with __syncthreads
    #pragma unroll
    for (int t = 0; t < 32; t++) { C[t][0] = C[t][1] = C[t][2] = C[t][3] = 0.f; }
    sweep_dual<1>(C, qH0, bOff, P0, P1, 98304u, tid);

    // epilogue: +bq, per-head norms, write Q (fp16) over QBUF (own rows only)
    float ssqA[4] = {0.f, 0.f, 0.f, 0.f}, ssqB[4] = {0.f, 0.f, 0.f, 0.f};
    #pragma unroll
    for (int t = 0; t < 32; t++) {
        int col = (t >> 4) * 128 + (t & 15) * 8 + (lane & 3) * 2;
        float v0 = C[t][0] + cst[col], v1 = C[t][1] + cst[col + 1];
        float v2 = C[t][2] + cst[col], v3 = C[t][3] + cst[col + 1];
        int hh = col >> 6;
        ssqA[hh] += v0 * v0 + v1 * v1;
        ssqB[hh] += v2 * v2 + v3 * v3;
        char* p = sma + QHo + (mb + (lane >> 2)) * 528 + col * 2;
        *(u32*)p = pk2h(v0, v1);
        *(u32*)(p + 8 * 528) = pk2h(v2, v3);
    }
    float rqA[4], rqB[4];
    #pragma unroll
    for (int hh = 0; hh < 4; hh++) {
        float s = ssqA[hh];
        s += __shfl_xor_sync(0xffffffffu, s, 1); s += __shfl_xor_sync(0xffffffffu, s, 2);
        rqA[hh] = 1.f / (sqrtf(s) + 1e-8f);
        s = ssqB[hh];
        s += __shfl_xor_sync(0xffffffffu, s, 1); s += __shfl_xor_sync(0xffffffffu, s, 2);
        rqB[hh] = 1.f / (sqrtf(s) + 1e-8f);
    }
    __syncthreads();

    // ---------- Phase C: dual-tier cosine attention ----------
    #pragma unroll 1
    for (int h = 0; h < 4; h++) {
        __syncthreads();   // all warps done with previous head's kv tiles
        {
            const uint4* s0 = g_knh[0][h];
            const uint4* s2 = g_vth[0][h]; const uint4* s3 = g_vtl[0][h];
            const uint4* s4 = g_knh[1][h];
            const uint4* s6 = g_vth[1][h]; const uint4* s7 = g_vtl[1][h];
            #pragma unroll
            for (int i = tid; i < 512; i += 256) {
                u32 d = (u32)(i >> 3) * 144 + (u32)(i & 7) * 16;
                CPA16(P0 + d,         (const void*)(s0 + i));
                CPA16(P0 + 18432 + d, (const void*)(s2 + i));
                CPA16(P0 + 27648 + d, (const void*)(s3 + i));
                CPA16(P1 + d,         (const void*)(s4 + i));
                CPA16(P1 + 18432 + d, (const void*)(s6 + i));
                CPA16(P1 + 27648 + d, (const void*)(s7 + i));
            }
            COMMIT();
            WAITG0();
        }
        __syncthreads();

        float rq0 = rqA[h], rq1 = rqB[h];
        float T[8][4];
        #pragma unroll
        for (int t = 0; t < 8; t++) { T[t][0] = T[t][1] = T[t][2] = T[t][3] = 0.f; }

        #pragma unroll 1
        for (int tier = 0; tier < 2; tier++) {
            u32 Pt = tier ? P1 : P0;
            // sim = Q_h @ kn^T (1-term fp16)
            float S[8][4];
            #pragma unroll
            for (int t = 0; t < 8; t++) { S[t][0] = S[t][1] = S[t][2] = S[t][3] = 0.f; }
            gemm_stage<4, 1>(S, qH0 + (u32)h * 128, Pt + bOff, Pt + bOff);

            float sc0 = tier ? aD0 : aF0, sc1 = tier ? aD1 : aF1;
            float mx0 = -1e30f, mx1 = -1e30f;
            #pragma unroll
            for (int t = 0; t < 8; t++) {
                S[t][0] *= rq0; S[t][1] *= rq0; S[t][2] *= rq1; S[t][3] *= rq1;
                mx0 = fmaxf(mx0, fmaxf(S[t][0], S[t][1]));
                mx1 = fmaxf(mx1, fmaxf(S[t][2], S[t][3]));
            }
            mx0 = fmaxf(mx0, __shfl_xor_sync(0xffffffffu, mx0, 1));
            mx0 = fmaxf(mx0, __shfl_xor_sync(0xffffffffu, mx0, 2));
            mx1 = fmaxf(mx1, __shfl_xor_sync(0xffffffffu, mx1, 1));
            mx1 = fmaxf(mx1, __shfl_xor_sync(0xffffffffu, mx1, 2));
            float su0 = 0.f, su1 = 0.f;
            #pragma unroll
            for (int t = 0; t < 8; t++) {
                S[t][0] = __expf(S[t][0] - mx0); S[t][1] = __expf(S[t][1] - mx0);
                S[t][2] = __expf(S[t][2] - mx1); S[t][3] = __expf(S[t][3] - mx1);
                su0 += S[t][0] + S[t][1];
                su1 += S[t][2] + S[t][3];
            }
            su0 += __shfl_xor_sync(0xffffffffu, su0, 1); su0 += __shfl_xor_sync(0xffffffffu, su0, 2);
            su1 += __shfl_xor_sync(0xffffffffu, su1, 1); su1 += __shfl_xor_sync(0xffffffffu, su1, 2);
            float iv0 = sc0 / su0, iv1 = sc1 / su1;

            u32 pH[8][2];
            #pragma unroll
            for (int t = 0; t < 8; t++) {
                pH[t][0] = pk2h(S[t][0] * iv0, S[t][1] * iv0);
                pH[t][1] = pk2h(S[t][2] * iv1, S[t][3] * iv1);
            }

            // T += P @ V (2-term fp16: Ph@Vh + Ph@Vl)
            #pragma unroll
            for (int kt = 0; kt < 4; kt++) {
                u32 a0 = pH[2*kt][0], a1 = pH[2*kt][1], a2 = pH[2*kt+1][0], a3 = pH[2*kt+1][1];
                #pragma unroll
                for (int np = 0; np < 4; np++) {
                    u32 b0, b1, b2, b3, d0, d1, d2, d3;
                    ldsm4(Pt + 18432 + bOff + np * 2304 + kt * 32, b0, b1, b2, b3);
                    ldsm4(Pt + 27648 + bOff + np * 2304 + kt * 32, d0, d1, d2, d3);
                    mmab(T[2*np],   a0, a1, a2, a3, b0, b1);
                    mmab(T[2*np],   a0, a1, a2, a3, d0, d1);
                    mmab(T[2*np+1], a0, a1, a2, a3, b2, b3);
                    mmab(T[2*np+1], a0, a1, a2, a3, d2, d3);
                }
            }
        }

        // write t_h (fp16) over Q_h in QBUF (own rows only)
        #pragma unroll
        for (int t = 0; t < 8; t++) {
            int col = h * 64 + t * 8 + (lane & 3) * 2;
            char* p = sma + QHo + (mb + (lane >> 2)) * 528 + col * 2;
            *(u32*)p = pk2h(T[t][0], T[t][1]);
            *(u32*)(p + 8 * 528) = pk2h(T[t][2], T[t][3]);
        }
        __syncwarp();
    }
    __syncthreads();

    // ---------- Phase D: out = t @ Wo^T + bo (N=256, 1-term fp16) ----------
    prefW<false>(P0, 163840u, tid);
    prefW<false>(P1, 163840u + 8192u, tid);
    #pragma unroll
    for (int t = 0; t < 32; t++) { C[t][0] = C[t][1] = C[t][2] = C[t][3] = 0.f; }
    sweep_dual<1>(C, qH0, bOff, P0, P1, 163840u, tid);

    #pragma unroll
    for (int t = 0; t < 32; t++) {
        int col = (t >> 4) * 128 + (t & 15) * 8 + (lane & 3) * 2;
        size_t r0 = m0 + mb + (lane >> 2);
        float2 o0 = make_float2(C[t][0] + cst[512 + col], C[t][1] + cst[512 + col + 1]);
        *(float2*)(outp + r0 * 256 + col) = o0;
        float2 o1 = make_float2(C[t][2] + cst[512 + col], C[t][3] + cst[512 + col + 1]);
        *(float2*)(outp + (r0 + 8) * 256 + col) = o1;
    }
}

extern "C" void kernel_launch(void* const* d_in, const int* in_sizes, int n_in,
                              void* d_out, int out_size) {
    (void)in_sizes; (void)n_in; (void)out_size;
    const float* query   = (const float*)d_in[0];
    const float* context = (const float*)d_in[1];
    const float* fk  = (const float*)d_in[2];
    const float* fv  = (const float*)d_in[3];
    const float* dk  = (const float*)d_in[4];
    const float* dv  = (const float*)d_in[5];
    const float* Wq  = (const float*)d_in[6];
    const float* bq  = (const float*)d_in[7];
    const float* Wg  = (const float*)d_in[8];
    const float* bg  = (const float*)d_in[9];
    const float* Wc1 = (const float*)d_in[10];
    const float* bc1 = (const float*)d_in[11];
    const float* Wc2 = (const float*)d_in[12];
    const float* bc2 = (const float*)d_in[13];
    const float* Wo  = (const float*)d_in[14];
    const float* bo  = (const float*)d_in[15];
    const float* mixl = (const float*)d_in[18];
    float* out = (float*)d_out;

    cudaFuncSetAttribute(miras_mma, cudaFuncAttributeMaxDynamicSharedMemorySize, SMEM_BYTES);

    prep_W<<<224, 256>>>(Wq, Wg, Wc1, Wo);
    prep_kv<<<2, 256>>>(fk, fv, dk, dv);
    miras_mma<<<512, 256, SMEM_BYTES>>>(query, context, bq, bg, bc1, Wc2, bc2, bo, mixl, out);
}

// round 16
// speedup vs baseline: 1.7132x; 1.0987x over previous
#include <cuda_runtime.h>
#include <cuda_fp16.h>

typedef unsigned long long u64;
typedef unsigned int u32;
typedef unsigned short u16;

// ---------------- smem layout (bytes) ----------------
#define QHo   0        // Q/t fp16: 128 rows x 264 halves (stride 528B) = 67584
#define P0o   67584    // ping buffer (36864): W chunk hi(18432)+lo(18432) / attn head tiles
#define P1o   104448   // pong buffer (36864)
#define CSTo  141312   // 1024 floats: bq(256) bg(256) bo(256) bc1(128) wc2(128)
#define SMEM_BYTES 145408

// ---------------- prepped global images (fp16) ----------------
// W images packed [kc][n][64]; elem bases: Wg=0, Wc1=65536, Wq=98304, Wo=163840
__device__ uint4 g_Wh_img[28672], g_Wl_img[28672];
__device__ uint4 g_knh[2][4][512];   // normalized keys [s][d] 64x64 (hi only)
__device__ uint4 g_vth[2][4][512];   // values transposed [d][s] 64x64 (hi only)

// ---------------- helpers ----------------
__device__ __forceinline__ u32 pk2h(float x, float y) {   // lo=x, hi=y
    u32 r; asm("cvt.rn.f16x2.f32 %0, %1, %2;" : "=r"(r) : "f"(y), "f"(x)); return r;
}
__device__ __forceinline__ void sp2(float x, float y, u32& h, u32& l) {
    __half hx = __float2half_rn(x), hy = __float2half_rn(y);
    h = (u32)__half_as_ushort(hx) | ((u32)__half_as_ushort(hy) << 16);
    __half lx = __float2half_rn(x - __half2float(hx));
    __half ly = __float2half_rn(y - __half2float(hy));
    l = (u32)__half_as_ushort(lx) | ((u32)__half_as_ushort(ly) << 16);
}
__device__ __forceinline__ u32 smaddr(const void* p) {
    u32 a;
    asm("{ .reg .u64 t; cvta.to.shared.u64 t, %1; cvt.u32.u64 %0, t; }" : "=r"(a) : "l"(p));
    return a;
}
__device__ __forceinline__ void ldsm4(u32 a, u32& r0, u32& r1, u32& r2, u32& r3) {
    asm volatile("ldmatrix.sync.aligned.m8n8.x4.shared.b16 {%0,%1,%2,%3}, [%4];"
                 : "=r"(r0), "=r"(r1), "=r"(r2), "=r"(r3) : "r"(a));
}
__device__ __forceinline__ void mmab(float* c, u32 a0, u32 a1, u32 a2, u32 a3, u32 b0, u32 b1) {
    asm volatile(
        "mma.sync.aligned.m16n8k16.row.col.f32.f16.f16.f32 "
        "{%0,%1,%2,%3}, {%4,%5,%6,%7}, {%8,%9}, {%0,%1,%2,%3};"
        : "+f"(c[0]), "+f"(c[1]), "+f"(c[2]), "+f"(c[3])
        : "r"(a0), "r"(a1), "r"(a2), "r"(a3), "r"(b0), "r"(b1));
}
__device__ __forceinline__ float tanha(float x) {
    float y; asm("tanh.approx.f32 %0, %1;" : "=f"(y) : "f"(x)); return y;
}
#define CPA16(d, s) asm volatile("cp.async.cg.shared.global [%0], [%1], 16;" :: "r"(d), "l"(s) : "memory")
#define COMMIT()    asm volatile("cp.async.commit_group;" ::: "memory")
#define WAITG0()    asm volatile("cp.async.wait_group 0;" ::: "memory")
#define WAITG1()    asm volatile("cp.async.wait_group 1;" ::: "memory")

// prefetch one 128x64 W chunk into buffer p; LO = also copy the lo plane
template<bool LO>
__device__ __forceinline__ void prefW(u32 p, u32 baseE, int tid) {
    const uint4* sH = g_Wh_img + (baseE >> 3);
    const uint4* sL = g_Wl_img + (baseE >> 3);
    #pragma unroll
    for (int i = tid; i < 1024; i += 256) {
        u32 d = p + (u32)(i >> 3) * 144 + (u32)(i & 7) * 16;
        CPA16(d, (const void*)(sH + i));
        if (LO) CPA16(d + 18432, (const void*)(sL + i));
    }
    COMMIT();
}

// prefetch one head's attention tiles into buffer p: knF@0, vF@9216, knD@18432, vD@27648
__device__ __forceinline__ void prefAttn(u32 p, int h, int tid) {
    const uint4* s0 = g_knh[0][h];
    const uint4* s1 = g_vth[0][h];
    const uint4* s2 = g_knh[1][h];
    const uint4* s3 = g_vth[1][h];
    #pragma unroll
    for (int i = tid; i < 512; i += 256) {
        u32 d = p + (u32)(i >> 3) * 144 + (u32)(i & 7) * 16;
        CPA16(d,         (const void*)(s0 + i));
        CPA16(d + 9216,  (const void*)(s1 + i));
        CPA16(d + 18432, (const void*)(s2 + i));
        CPA16(d + 27648, (const void*)(s3 + i));
    }
    COMMIT();
}

// one K=64 stage: C[2*NP][4] += A(16 rows,64 cols) @ B(NP*16 rows,64 cols)^T
// TERMS: 1 = Ah@Bh, 2 = +Ah@Bl
template<int NP, int TERMS>
__device__ __forceinline__ void gemm_stage(float (*C)[4], u32 aH, u32 bH, u32 bL) {
    #pragma unroll
    for (int kt = 0; kt < 4; kt++) {
        u32 a0, a1, a2, a3;
        ldsm4(aH + kt * 32, a0, a1, a2, a3);
        #pragma unroll
        for (int np = 0; np < NP; np++) {
            u32 b0, b1, b2, b3, d0, d1, d2, d3;
            ldsm4(bH + np * 2304 + kt * 32, b0, b1, b2, b3);
            if (TERMS >= 2) ldsm4(bL + np * 2304 + kt * 32, d0, d1, d2, d3);
            mmab(C[2 * np], a0, a1, a2, a3, b0, b1);
            if (TERMS >= 2) mmab(C[2 * np], a0, a1, a2, a3, d0, d1);
            mmab(C[2 * np + 1], a0, a1, a2, a3, b2, b3);
            if (TERMS >= 2) mmab(C[2 * np + 1], a0, a1, a2, a3, d2, d3);
        }
    }
}

// dual-half sweep (N=256): 8 chunks, C[0..15]=half0, C[16..31]=half1; prolog chunks 0,1 committed
template<int TERMS>
__device__ __forceinline__ void sweep_dual(float (*C)[4], u32 aH0, u32 bOff,
                                           u32 P0, u32 P1, u32 baseE, int tid) {
    #pragma unroll 1
    for (int kc = 0; kc < 4; kc++) {
        WAITG1();
        __syncthreads();
        gemm_stage<8, TERMS>(C, aH0 + (u32)kc * 128, P0 + bOff, P0 + 18432 + bOff);
        if (kc < 3) { __syncthreads(); prefW<(TERMS >= 2)>(P0, baseE + (u32)(kc * 2 + 2) * 8192, tid); }
        if (kc == 3) { WAITG0(); } else { WAITG1(); }
        __syncthreads();
        gemm_stage<8, TERMS>(C + 16, aH0 + (u32)kc * 128, P1 + bOff, P1 + 18432 + bOff);
        if (kc < 3) { __syncthreads(); prefW<(TERMS >= 2)>(P1, baseE + (u32)(kc * 2 + 3) * 8192, tid); }
    }
    __syncthreads();
}

// single-half sweep (N=128): 4 chunks into one C set; prolog chunks 0,1 committed
template<int TERMS>
__device__ __forceinline__ void sweep_single(float (*C)[4], u32 aH0, u32 bOff,
                                             u32 P0, u32 P1, u32 baseE, int tid) {
    #pragma unroll 1
    for (int s = 0; s < 4; s++) {
        if (s == 3) { WAITG0(); } else { WAITG1(); }
        __syncthreads();
        u32 pb = (s & 1) ? P1 : P0;
        gemm_stage<8, TERMS>(C, aH0 + (u32)s * 128, pb + bOff, pb + 18432 + bOff);
        if (s < 2) { __syncthreads(); prefW<(TERMS >= 2)>(pb, baseE + (u32)(s + 2) * 8192, tid); }
    }
    __syncthreads();
}

// stage fp32 [128x256] -> QBUF fp16 (stride 528)
__device__ __forceinline__ void stageQ(char* sma, const float* __restrict__ src, int tid) {
    #pragma unroll 4
    for (int i = tid; i < 8192; i += 256) {
        int r = i >> 6, c4 = i & 63;
        float4 v = *(const float4*)(src + (size_t)r * 256 + c4 * 4);
        u32 h0 = pk2h(v.x, v.y), h1 = pk2h(v.z, v.w);
        *(u64*)(sma + QHo + r * 528 + c4 * 8) = (u64)h0 | ((u64)h1 << 32);
    }
}

// ---------------- prep kernels ----------------
__global__ void prep_W(const float* __restrict__ Wq, const float* __restrict__ Wg,
                       const float* __restrict__ Wc1, const float* __restrict__ Wo) {
    int t = blockIdx.x * blockDim.x + threadIdx.x;   // 0..57343
    const float* src; int N; u32 base; int tt;
    if (t < 16384)      { src = Wg;  N = 256; base = 0u;      tt = t; }
    else if (t < 24576) { src = Wc1; N = 128; base = 65536u;  tt = t - 16384; }
    else if (t < 40960) { src = Wq;  N = 256; base = 98304u;  tt = t - 24576; }
    else                { src = Wo;  N = 256; base = 163840u; tt = t - 40960; }
    int n = tt >> 6, c4 = tt & 63;
    int kc = c4 >> 4, kk = (c4 & 15) * 4;
    float4 v = *(const float4*)(src + (size_t)n * 256 + c4 * 4);
    u32 h0, l0, h1, l1;
    sp2(v.x, v.y, h0, l0);
    sp2(v.z, v.w, h1, l1);
    u32 e = base + (u32)(kc * N + n) * 64 + (u32)kk;
    ((u64*)g_Wh_img)[e >> 2] = (u64)h0 | ((u64)h1 << 32);
    ((u64*)g_Wl_img)[e >> 2] = (u64)l0 | ((u64)l1 << 32);
}

__global__ void prep_kv(const float* __restrict__ fk, const float* __restrict__ fv,
                        const float* __restrict__ dk, const float* __restrict__ dv) {
    int t = blockIdx.x * blockDim.x + threadIdx.x;
    if (t >= 512) return;
    int tier = t >> 8, rem = t & 255, h = rem >> 6, s = rem & 63;
    const float* K = (tier ? dk : fk) + (h * 64 + s) * 64;
    const float* V = (tier ? dv : fv) + (h * 64 + s) * 64;
    float ss = 0.f;
    for (int d = 0; d < 64; d++) { float v = K[d]; ss += v * v; }
    float r = 1.0f / (sqrtf(ss) + 1e-8f);
    u16* knh = (u16*)g_knh[tier][h];
    u16* vth = (u16*)g_vth[tier][h];
    for (int d = 0; d < 64; d++) {
        knh[s * 64 + d] = __half_as_ushort(__float2half_rn(K[d] * r));
        vth[d * 64 + s] = __half_as_ushort(__float2half_rn(V[d]));
    }
}

// ---------------- main kernel ----------------
__global__ void __launch_bounds__(256, 1) miras_mma(
    const float* __restrict__ query, const float* __restrict__ context,
    const float* __restrict__ bq, const float* __restrict__ bg,
    const float* __restrict__ bc1, const float* __restrict__ Wc2,
    const float* __restrict__ bc2, const float* __restrict__ bo,
    const float* __restrict__ mixl, float* __restrict__ outp)
{
    extern __shared__ char sma[];
    const u32 sb = smaddr(sma);
    const int tid = threadIdx.x, lane = tid & 31, warp = tid >> 5;
    const int mb = warp * 16;
    const size_t m0 = (size_t)blockIdx.x * 128;
    float* cst = (float*)(sma + CSTo);
    const u32 P0 = sb + P0o, P1 = sb + P1o;

    { int i = tid; cst[i] = bq[i]; cst[256 + i] = bg[i]; cst[512 + i] = bo[i]; }
    if (tid < 128) { cst[768 + tid] = bc1[tid]; cst[896 + tid] = Wc2[tid]; }
    const float mixl_v = __ldg(mixl), bc2v = __ldg(bc2);

    // lane-resolved ldmatrix offsets
    const u32 arow = (u32)(((lane >> 3) & 1) * 8 + (lane & 7));
    const u32 aOffQ = (u32)(mb + arow) * 528 + (u32)(lane >> 4) * 16;
    const u32 bOff  = (u32)(((lane >> 4) & 1) * 8 + (lane & 7)) * 144 + (u32)((lane >> 3) & 1) * 16;
    const u32 qH0 = sb + QHo + aOffQ;

    float C[32][4];

    // ---------- Phase A: gate (N=256, 1-term fp16) ----------
    prefW<false>(P0, 0u, tid);
    prefW<false>(P1, 8192u, tid);
    stageQ(sma, context + m0 * 256, tid);
    #pragma unroll
    for (int t = 0; t < 32; t++) { C[t][0] = C[t][1] = C[t][2] = C[t][3] = 0.f; }
    sweep_dual<1>(C, qH0, bOff, P0, P1, 0u, tid);

    // conf prolog behind gate epilogue
    prefW<false>(P0, 65536u, tid);
    prefW<false>(P1, 65536u + 8192u, tid);

    float ga0 = 0.f, ga1 = 0.f;
    #pragma unroll
    for (int t = 0; t < 32; t++) {
        int col = (t >> 4) * 128 + (t & 15) * 8 + (lane & 3) * 2;
        ga0 += tanha(C[t][0] + cst[256 + col]) + tanha(C[t][1] + cst[256 + col + 1]);
        ga1 += tanha(C[t][2] + cst[256 + col]) + tanha(C[t][3] + cst[256 + col + 1]);
    }

    // ---------- conf (N=128, 1-term fp16) ----------
    #pragma unroll
    for (int t = 0; t < 16; t++) { C[t][0] = C[t][1] = C[t][2] = C[t][3] = 0.f; }
    sweep_single<1>(C, qH0, bOff, P0, P1, 65536u, tid);

    // Wq prolog behind conf epilogue + query staging
    prefW<false>(P0, 98304u, tid);
    prefW<false>(P1, 98304u + 8192u, tid);

    float ca0 = 0.f, ca1 = 0.f;
    #pragma unroll
    for (int t = 0; t < 16; t++) {
        int col = t * 8 + (lane & 3) * 2;
        ca0 += tanha(C[t][0] + cst[768 + col]) * cst[896 + col]
             + tanha(C[t][1] + cst[768 + col + 1]) * cst[896 + col + 1];
        ca1 += tanha(C[t][2] + cst[768 + col]) * cst[896 + col]
             + tanha(C[t][3] + cst[768 + col + 1]) * cst[896 + col + 1];
    }
    stageQ(sma, query + m0 * 256, tid);          // safe: conf sweep ended with __syncthreads

    ga0 += __shfl_xor_sync(0xffffffffu, ga0, 1); ga0 += __shfl_xor_sync(0xffffffffu, ga0, 2);
    ga1 += __shfl_xor_sync(0xffffffffu, ga1, 1); ga1 += __shfl_xor_sync(0xffffffffu, ga1, 2);
    ca0 += __shfl_xor_sync(0xffffffffu, ca0, 1); ca0 += __shfl_xor_sync(0xffffffffu, ca0, 2);
    ca1 += __shfl_xor_sync(0xffffffffu, ca1, 1); ca1 += __shfl_xor_sync(0xffffffffu, ca1, 2);
    float mix0 = 1.f / (1.f + __expf(-(mixl_v + ga0 * (1.f / 256.f))));
    float mix1 = 1.f / (1.f + __expf(-(mixl_v + ga1 * (1.f / 256.f))));
    float cf0 = 1.f / (1.f + __expf(-(ca0 + bc2v)));
    float cf1 = 1.f / (1.f + __expf(-(ca1 + bc2v)));
    float aF0 = mix0 * cf0, aD0 = (1.f - mix0) * cf0;
    float aF1 = mix1 * cf1, aD1 = (1.f - mix1) * cf1;

    // ---------- Phase B: Q = query @ Wq^T + bq (N=256, 1-term fp16) ----------
    #pragma unroll
    for (int t = 0; t < 32; t++) { C[t][0] = C[t][1] = C[t][2] = C[t][3] = 0.f; }
    sweep_dual<1>(C, qH0, bOff, P0, P1, 98304u, tid);

    // attention head 0/1 prolog behind the Q epilogue
    prefAttn(P0, 0, tid);
    prefAttn(P1, 1, tid);

    // epilogue: +bq, per-head norms, write Q (fp16) over QBUF (own rows only)
    float ssqA[4] = {0.f, 0.f, 0.f, 0.f}, ssqB[4] = {0.f, 0.f, 0.f, 0.f};
    #pragma unroll
    for (int t = 0; t < 32; t++) {
        int col = (t >> 4) * 128 + (t & 15) * 8 + (lane & 3) * 2;
        float v0 = C[t][0] + cst[col], v1 = C[t][1] + cst[col + 1];
        float v2 = C[t][2] + cst[col], v3 = C[t][3] + cst[col + 1];
        int hh = col >> 6;
        ssqA[hh] += v0 * v0 + v1 * v1;
        ssqB[hh] += v2 * v2 + v3 * v3;
        char* p = sma + QHo + (mb + (lane >> 2)) * 528 + col * 2;
        *(u32*)p = pk2h(v0, v1);
        *(u32*)(p + 8 * 528) = pk2h(v2, v3);
    }
    float rqA[4], rqB[4];
    #pragma unroll
    for (int hh = 0; hh < 4; hh++) {
        float s = ssqA[hh];
        s += __shfl_xor_sync(0xffffffffu, s, 1); s += __shfl_xor_sync(0xffffffffu, s, 2);
        rqA[hh] = 1.f / (sqrtf(s) + 1e-8f);
        s = ssqB[hh];
        s += __shfl_xor_sync(0xffffffffu, s, 1); s += __shfl_xor_sync(0xffffffffu, s, 2);
        rqB[hh] = 1.f / (sqrtf(s) + 1e-8f);
    }
    __syncthreads();

    // ---------- Phase C: dual-tier attention, head-level double buffering ----------
    #pragma unroll 1
    for (int h = 0; h < 4; h++) {
        if (h == 3) { WAITG0(); } else { WAITG1(); }
        __syncthreads();
        const u32 Pb = (h & 1) ? P1 : P0;

        float rq0 = rqA[h], rq1 = rqB[h];
        float T[8][4];
        #pragma unroll
        for (int t = 0; t < 8; t++) { T[t][0] = T[t][1] = T[t][2] = T[t][3] = 0.f; }

        #pragma unroll 1
        for (int tier = 0; tier < 2; tier++) {
            const u32 kn = Pb + (u32)tier * 18432;
            const u32 vt = kn + 9216;
            // sim = Q_h @ kn^T (1-term fp16)
            float S[8][4];
            #pragma unroll
            for (int t = 0; t < 8; t++) { S[t][0] = S[t][1] = S[t][2] = S[t][3] = 0.f; }
            gemm_stage<4, 1>(S, qH0 + (u32)h * 128, kn + bOff, kn + bOff);

            float sc0 = tier ? aD0 : aF0, sc1 = tier ? aD1 : aF1;
            float mx0 = -1e30f, mx1 = -1e30f;
            #pragma unroll
            for (int t = 0; t < 8; t++) {
                S[t][0] *= rq0; S[t][1] *= rq0; S[t][2] *= rq1; S[t][3] *= rq1;
                mx0 = fmaxf(mx0, fmaxf(S[t][0], S[t][1]));
                mx1 = fmaxf(mx1, fmaxf(S[t][2], S[t][3]));
            }
            mx0 = fmaxf(mx0, __shfl_xor_sync(0xffffffffu, mx0, 1));
            mx0 = fmaxf(mx0, __shfl_xor_sync(0xffffffffu, mx0, 2));
            mx1 = fmaxf(mx1, __shfl_xor_sync(0xffffffffu, mx1, 1));
            mx1 = fmaxf(mx1, __shfl_xor_sync(0xffffffffu, mx1, 2));
            float su0 = 0.f, su1 = 0.f;
            #pragma unroll
            for (int t = 0; t < 8; t++) {
                S[t][0] = __expf(S[t][0] - mx0); S[t][1] = __expf(S[t][1] - mx0);
                S[t][2] = __expf(S[t][2] - mx1); S[t][3] = __expf(S[t][3] - mx1);
                su0 += S[t][0] + S[t][1];
                su1 += S[t][2] + S[t][3];
            }
            su0 += __shfl_xor_sync(0xffffffffu, su0, 1); su0 += __shfl_xor_sync(0xffffffffu, su0, 2);
            su1 += __shfl_xor_sync(0xffffffffu, su1, 1); su1 += __shfl_xor_sync(0xffffffffu, su1, 2);
            float iv0 = sc0 / su0, iv1 = sc1 / su1;

            u32 pH[8][2];
            #pragma unroll
            for (int t = 0; t < 8; t++) {
                pH[t][0] = pk2h(S[t][0] * iv0, S[t][1] * iv0);
                pH[t][1] = pk2h(S[t][2] * iv1, S[t][3] * iv1);
            }

            // T += P @ V (1-term fp16)
            #pragma unroll
            for (int kt = 0; kt < 4; kt++) {
                u32 a0 = pH[2*kt][0], a1 = pH[2*kt][1], a2 = pH[2*kt+1][0], a3 = pH[2*kt+1][1];
                #pragma unroll
                for (int np = 0; np < 4; np++) {
                    u32 b0, b1, b2, b3;
                    ldsm4(vt + bOff + np * 2304 + kt * 32, b0, b1, b2, b3);
                    mmab(T[2*np],   a0, a1, a2, a3, b0, b1);
                    mmab(T[2*np+1], a0, a1, a2, a3, b2, b3);
                }
            }
        }

        __syncthreads();                        // all warps done reading Pb
        if (h < 2) prefAttn(Pb, h + 2, tid);    // refill with head h+2

        // write t_h (fp16) over Q_h in QBUF (own rows only)
        #pragma unroll
        for (int t = 0; t < 8; t++) {
            int col = h * 64 + t * 8 + (lane & 3) * 2;
            char* p = sma + QHo + (mb + (lane >> 2)) * 528 + col * 2;
            *(u32*)p = pk2h(T[t][0], T[t][1]);
            *(u32*)(p + 8 * 528) = pk2h(T[t][2], T[t][3]);
        }
        __syncwarp();
    }
    __syncthreads();

    // ---------- Phase D: out = t @ Wo^T + bo (N=256, 1-term fp16) ----------
    prefW<false>(P0, 163840u, tid);
    prefW<false>(P1, 163840u + 8192u, tid);
    #pragma unroll
    for (int t = 0; t < 32; t++) { C[t][0] = C[t][1] = C[t][2] = C[t][3] = 0.f; }
    sweep_dual<1>(C, qH0, bOff, P0, P1, 163840u, tid);

    #pragma unroll
    for (int t = 0; t < 32; t++) {
        int col = (t >> 4) * 128 + (t & 15) * 8 + (lane & 3) * 2;
        size_t r0 = m0 + mb + (lane >> 2);
        float2 o0 = make_float2(C[t][0] + cst[512 + col], C[t][1] + cst[512 + col + 1]);
        *(float2*)(outp + r0 * 256 + col) = o0;
        float2 o1 = make_float2(C[t][2] + cst[512 + col], C[t][3] + cst[512 + col + 1]);
        *(float2*)(outp + (r0 + 8) * 256 + col) = o1;
    }
}

extern "C" void kernel_launch(void* const* d_in, const int* in_sizes, int n_in,
                              void* d_out, int out_size) {
    (void)in_sizes; (void)n_in; (void)out_size;
    const float* query   = (const float*)d_in[0];
    const float* context = (const float*)d_in[1];
    const float* fk  = (const float*)d_in[2];
    const float* fv  = (const float*)d_in[3];
    const float* dk  = (const float*)d_in[4];
    const float* dv  = (const float*)d_in[5];
    const float* Wq  = (const float*)d_in[6];
    const float* bq  = (const float*)d_in[7];
    const float* Wg  = (const float*)d_in[8];
    const float* bg  = (const float*)d_in[9];
    const float* Wc1 = (const float*)d_in[10];
    const float* bc1 = (const float*)d_in[11];
    const float* Wc2 = (const float*)d_in[12];
    const float* bc2 = (const float*)d_in[13];
    const float* Wo  = (const float*)d_in[14];
    const float* bo  = (const float*)d_in[15];
    const float* mixl = (const float*)d_in[18];
    float* out = (float*)d_out;

    cudaFuncSetAttribute(miras_mma, cudaFuncAttributeMaxDynamicSharedMemorySize, SMEM_BYTES);

    prep_W<<<224, 256>>>(Wq, Wg, Wc1, Wo);
    prep_kv<<<2, 256>>>(fk, fv, dk, dv);
    miras_mma<<<512, 256, SMEM_BYTES>>>(query, context, bq, bg, bc1, Wc2, bc2, bo, mixl, out);
}